// round 4
// baseline (speedup 1.0000x reference)
#include <cuda_runtime.h>

#define TT 8192
#define CC 64
#define BDIM 1024
#define HDIM 512
#define LOG2T 13
// Conflict-free padding: +2 float2 per 16.
#define PIDX(i) ((i) + (((i) >> 4) << 1))
#define SMEMN (TT + ((TT >> 4) << 1))   // 9216 float2 = 72 KB per buffer

__device__ __forceinline__ float2 cadd(float2 a, float2 b){ return make_float2(a.x+b.x, a.y+b.y); }
__device__ __forceinline__ float2 csub(float2 a, float2 b){ return make_float2(a.x-b.x, a.y-b.y); }
__device__ __forceinline__ float2 cmulf(float2 a, float2 b){
    return make_float2(fmaf(a.x, b.x, -a.y*b.y), fmaf(a.x, b.y, a.y*b.x));
}
__device__ __forceinline__ float2 cmuli (float2 a){ return make_float2(-a.y,  a.x); }  // * i
__device__ __forceinline__ float2 cmulni(float2 a){ return make_float2( a.y, -a.x); }  // * -i

#define C45F 0.70710678118654752f
#define C8F  0.92387953251128674f
#define S8F  0.38268343236508977f
__device__ __forceinline__ float2 mul_psi1(float2 a){ return make_float2(C45F*(a.x+a.y), C45F*(a.y-a.x)); }
__device__ __forceinline__ float2 mul_psi3(float2 a){ return make_float2(C45F*(a.y-a.x), -C45F*(a.x+a.y)); }
__device__ __forceinline__ float2 mul_om1 (float2 a){ return make_float2(C45F*(a.x-a.y), C45F*(a.x+a.y)); }
__device__ __forceinline__ float2 mul_om3 (float2 a){ return make_float2(-C45F*(a.x+a.y), C45F*(a.x-a.y)); }

// Forward DIF radix-8 (3 fused stages), legs stride s, twiddle w1 = e^{-i pi j/(4s)}.
__device__ __forceinline__ void r8_dif(float2* x, float2 w1) {
    float2 w2 = cmulf(w1, w1), w4 = cmulf(w2, w2);
    float2 y[8];
    #pragma unroll
    for (int j = 0; j < 4; ++j) { y[j] = cadd(x[j], x[j+4]); y[j+4] = csub(x[j], x[j+4]); }
    y[4] = cmulf(y[4], w1);
    y[5] = mul_psi1(cmulf(y[5], w1));
    y[6] = cmulni (cmulf(y[6], w1));
    y[7] = mul_psi3(cmulf(y[7], w1));
    float2 z[8];
    z[0]=cadd(y[0],y[2]); z[2]=cmulf (csub(y[0],y[2]), w2);
    z[1]=cadd(y[1],y[3]); z[3]=cmulni(cmulf(csub(y[1],y[3]), w2));
    z[4]=cadd(y[4],y[6]); z[6]=cmulf (csub(y[4],y[6]), w2);
    z[5]=cadd(y[5],y[7]); z[7]=cmulni(cmulf(csub(y[5],y[7]), w2));
    x[0]=cadd(z[0],z[1]); x[1]=cmulf(csub(z[0],z[1]), w4);
    x[2]=cadd(z[2],z[3]); x[3]=cmulf(csub(z[2],z[3]), w4);
    x[4]=cadd(z[4],z[5]); x[5]=cmulf(csub(z[4],z[5]), w4);
    x[6]=cadd(z[6],z[7]); x[7]=cmulf(csub(z[6],z[7]), w4);
}

// Inverse DIT radix-8 (3 fused stages), legs stride m, v3 = e^{+i pi j/(4m)}.
__device__ __forceinline__ void r8_dit(float2* x, float2 v3) {
    float2 v2 = cmulf(v3, v3), v1 = cmulf(v2, v2);
    float2 y[8], t;
    t=cmulf(v1,x[1]); y[0]=cadd(x[0],t); y[1]=csub(x[0],t);
    t=cmulf(v1,x[3]); y[2]=cadd(x[2],t); y[3]=csub(x[2],t);
    t=cmulf(v1,x[5]); y[4]=cadd(x[4],t); y[5]=csub(x[4],t);
    t=cmulf(v1,x[7]); y[6]=cadd(x[6],t); y[7]=csub(x[6],t);
    float2 z[8];
    t=cmulf(v2,y[2]);        z[0]=cadd(y[0],t); z[2]=csub(y[0],t);
    t=cmuli(cmulf(v2,y[3])); z[1]=cadd(y[1],t); z[3]=csub(y[1],t);
    t=cmulf(v2,y[6]);        z[4]=cadd(y[4],t); z[6]=csub(y[4],t);
    t=cmuli(cmulf(v2,y[7])); z[5]=cadd(y[5],t); z[7]=csub(y[5],t);
    t=cmulf(v3,z[4]);          x[0]=cadd(z[0],t); x[4]=csub(z[0],t);
    t=mul_om1(cmulf(v3,z[5])); x[1]=cadd(z[1],t); x[5]=csub(z[1],t);
    t=cmuli  (cmulf(v3,z[6])); x[2]=cadd(z[2],t); x[6]=csub(z[2],t);
    t=mul_om3(cmulf(v3,z[7])); x[3]=cadd(z[3],t); x[7]=csub(z[3],t);
}

// Forward DIF radix-16 on 16 consecutive elements. Constant twiddles.
__device__ __forceinline__ void r16_dif(float2* x) {
    float2 y[16];
    #pragma unroll
    for (int j = 0; j < 8; ++j) { y[j] = cadd(x[j], x[j+8]); y[j+8] = csub(x[j], x[j+8]); }
    y[9]  = cmulf(y[9],  make_float2( C8F, -S8F));
    y[10] = mul_psi1(y[10]);
    y[11] = cmulf(y[11], make_float2( S8F, -C8F));
    y[12] = cmulni(y[12]);
    y[13] = cmulf(y[13], make_float2(-S8F, -C8F));
    y[14] = mul_psi3(y[14]);
    y[15] = cmulf(y[15], make_float2(-C8F, -S8F));
    float2 z[16];
    #pragma unroll
    for (int g = 0; g < 16; g += 8) {
        #pragma unroll
        for (int j = 0; j < 4; ++j) { z[g+j] = cadd(y[g+j], y[g+j+4]); z[g+j+4] = csub(y[g+j], y[g+j+4]); }
        z[g+5] = mul_psi1(z[g+5]);
        z[g+6] = cmulni (z[g+6]);
        z[g+7] = mul_psi3(z[g+7]);
    }
    float2 w[16];
    #pragma unroll
    for (int g = 0; g < 16; g += 4) {
        w[g+0]=cadd(z[g+0],z[g+2]); w[g+2]=csub(z[g+0],z[g+2]);
        w[g+1]=cadd(z[g+1],z[g+3]); w[g+3]=cmulni(csub(z[g+1],z[g+3]));
    }
    #pragma unroll
    for (int g = 0; g < 16; g += 2) { x[g] = cadd(w[g], w[g+1]); x[g+1] = csub(w[g], w[g+1]); }
}

// Inverse DIT radix-16 on 16 consecutive elements. Constant twiddles.
__device__ __forceinline__ void r16_dit(float2* x) {
    float2 y[16];
    #pragma unroll
    for (int g = 0; g < 16; g += 2) { y[g] = cadd(x[g], x[g+1]); y[g+1] = csub(x[g], x[g+1]); }
    float2 z[16];
    #pragma unroll
    for (int g = 0; g < 16; g += 4) {
        z[g+0]=cadd(y[g+0],y[g+2]); z[g+2]=csub(y[g+0],y[g+2]);
        float2 t = cmuli(y[g+3]);
        z[g+1]=cadd(y[g+1],t); z[g+3]=csub(y[g+1],t);
    }
    float2 w[16];
    #pragma unroll
    for (int g = 0; g < 16; g += 8) {
        float2 t0 = z[g+4];          w[g+0]=cadd(z[g+0],t0); w[g+4]=csub(z[g+0],t0);
        float2 t1 = mul_om1(z[g+5]); w[g+1]=cadd(z[g+1],t1); w[g+5]=csub(z[g+1],t1);
        float2 t2 = cmuli  (z[g+6]); w[g+2]=cadd(z[g+2],t2); w[g+6]=csub(z[g+2],t2);
        float2 t3 = mul_om3(z[g+7]); w[g+3]=cadd(z[g+3],t3); w[g+7]=csub(z[g+3],t3);
    }
    float2 t;
    t = w[8];                                 x[0]=cadd(w[0],t); x[8] =csub(w[0],t);
    t = cmulf(w[9],  make_float2( C8F, S8F)); x[1]=cadd(w[1],t); x[9] =csub(w[1],t);
    t = mul_om1(w[10]);                       x[2]=cadd(w[2],t); x[10]=csub(w[2],t);
    t = cmulf(w[11], make_float2( S8F, C8F)); x[3]=cadd(w[3],t); x[11]=csub(w[3],t);
    t = cmuli(w[12]);                         x[4]=cadd(w[4],t); x[12]=csub(w[4],t);
    t = cmulf(w[13], make_float2(-S8F, C8F)); x[5]=cadd(w[5],t); x[13]=csub(w[5],t);
    t = mul_om3(w[14]);                       x[6]=cadd(w[6],t); x[14]=csub(w[6],t);
    t = cmulf(w[15], make_float2(-C8F, S8F)); x[7]=cadd(w[7],t); x[15]=csub(w[7],t);
}

__global__ void __launch_bounds__(BDIM, 1)
surrogate_kernel(const float* __restrict__ wave,
                 const float* __restrict__ phases,
                 const float* __restrict__ mask,
                 float* __restrict__ out)
{
    extern __shared__ float2 buf[];   // 2 * SMEMN float2 = 144 KB
    const int tid = threadIdx.x;
    const int blk = blockIdx.x;
    const int b  = blk >> 4;          // 16 channel-quads per batch
    const int c0 = (blk & 15) * 4;    // 4 channels per CTA

    const bool sel0 = mask[b * CC + c0 + 0] < 0.5f;
    const bool sel1 = mask[b * CC + c0 + 1] < 0.5f;
    const bool sel2 = mask[b * CC + c0 + 2] < 0.5f;
    const bool sel3 = mask[b * CC + c0 + 3] < 0.5f;

    const float4* wrow = (const float4*)(wave + ((size_t)b * TT) * CC + c0);  // stride 16 float4/row
    float4*       orow = (float4*)      (out  + ((size_t)b * TT) * CC + c0);

    // No channel selected: pure float4 copy.
    if (!(sel0 | sel1 | sel2 | sel3)) {
        for (int t = tid; t < TT; t += BDIM)
            orow[(size_t)t * (CC/4)] = wrow[(size_t)t * (CC/4)];
        return;
    }

    // ---- Staging: cooperative float4 load -> two complex buffers ----
    for (int t = tid; t < TT; t += BDIM) {
        float4 v = wrow[(size_t)t * (CC/4)];
        buf[PIDX(t)]         = make_float2(v.x, v.y);
        buf[SMEMN + PIDX(t)] = make_float2(v.z, v.w);
    }
    __syncthreads();

    const int half = tid >> 9;        // 0: channels c0,c0+1; 1: channels c0+2,c0+3
    const int ltid = tid & (HDIM - 1);
    float2* sb = buf + half * SMEMN;
    const bool act = half ? (sel2 | sel3) : (sel0 | sel1);

    const float PI_F   = 3.14159265358979f;
    const float TWO_PI = 6.28318530717959f;

    // ---- Pass A (fwd radix-8, s=1024) ----
    if (act) {
        #pragma unroll
        for (int it = 0; it < 2; ++it) {
            int q = ltid + it * HDIM;
            float2 x[8];
            #pragma unroll
            for (int j = 0; j < 8; ++j) x[j] = sb[PIDX(q + 1024 * j)];
            float s, c; __sincosf(-PI_F * (float)q * (1.0f/4096.0f), &s, &c);
            r8_dif(x, make_float2(c, s));
            #pragma unroll
            for (int j = 0; j < 8; ++j) sb[PIDX(q + 1024 * j)] = x[j];
        }
    }
    __syncthreads();

    // ---- Pass B (fwd radix-8, s=128) ----
    if (act) {
        #pragma unroll
        for (int it = 0; it < 2; ++it) {
            int q = ltid + it * HDIM;
            int t = q & 127;
            int d = ((q >> 7) << 10) + t;
            float2 x[8];
            #pragma unroll
            for (int j = 0; j < 8; ++j) x[j] = sb[PIDX(d + 128 * j)];
            float s, c; __sincosf(-PI_F * (float)t * (1.0f/512.0f), &s, &c);
            r8_dif(x, make_float2(c, s));
            #pragma unroll
            for (int j = 0; j < 8; ++j) sb[PIDX(d + 128 * j)] = x[j];
        }
    }
    __syncthreads();

    // ---- Pass C (fwd radix-8, s=16) ----
    if (act) {
        #pragma unroll
        for (int it = 0; it < 2; ++it) {
            int q = ltid + it * HDIM;
            int t = q & 15;
            int d = ((q >> 4) << 7) + t;
            float2 x[8];
            #pragma unroll
            for (int j = 0; j < 8; ++j) x[j] = sb[PIDX(d + 16 * j)];
            float s, c; __sincosf(-PI_F * (float)t * (1.0f/64.0f), &s, &c);
            r8_dif(x, make_float2(c, s));
            #pragma unroll
            for (int j = 0; j < 8; ++j) sb[PIDX(d + 16 * j)] = x[j];
        }
    }
    __syncthreads();

    // ---- Pass D (fwd radix-16, contiguous) ----
    if (act) {
        float4* p4 = (float4*)(sb + 18 * ltid);
        float2 x[16];
        #pragma unroll
        for (int k = 0; k < 8; ++k) {
            float4 v = p4[k];
            x[2*k]   = make_float2(v.x, v.y);
            x[2*k+1] = make_float2(v.z, v.w);
        }
        r16_dif(x);
        #pragma unroll
        for (int k = 0; k < 8; ++k)
            p4[k] = make_float4(x[2*k].x, x[2*k].y, x[2*k+1].x, x[2*k+1].y);
    }
    __syncthreads();

    // ---- Spectral stage (bit-reversed domain) ----
    if (act) {
        const float* pbase = phases + ((size_t)b * TT) * CC + c0 + 2 * half;
        for (int pos = ltid; pos < TT; pos += HDIM) {
            int k = __brev(pos) >> (32 - LOG2T);
            if (k > TT / 2) continue;
            int kn = (TT - k) & (TT - 1);
            int pn = __brev(kn) >> (32 - LOG2T);
            float2 Zk = sb[PIDX(pos)];
            float2 Zn = sb[PIDX(pn)];
            float re0 = 0.5f * (Zk.x + Zn.x), im0 = 0.5f * (Zk.y - Zn.y);
            float re1 = 0.5f * (Zk.y + Zn.y), im1 = 0.5f * (Zn.x - Zk.x);
            float A0 = sqrtf(fmaf(re0, re0, im0 * im0));
            float A1 = sqrtf(fmaf(re1, re1, im1 * im1));
            float2 phk = *(const float2*)(pbase + (size_t)k  * CC);
            float2 phn = *(const float2*)(pbase + (size_t)kn * CC);
            float s0k, c0k, s0n, c0n, s1k, c1k, s1n, c1n;
            __sincosf(fmaf(phk.x, TWO_PI, -PI_F), &s0k, &c0k); s0k = -s0k; c0k = -c0k;
            __sincosf(fmaf(phn.x, TWO_PI, -PI_F), &s0n, &c0n); s0n = -s0n; c0n = -c0n;
            __sincosf(fmaf(phk.y, TWO_PI, -PI_F), &s1k, &c1k); s1k = -s1k; c1k = -c1k;
            __sincosf(fmaf(phn.y, TWO_PI, -PI_F), &s1n, &c1n); s1n = -s1n; c1n = -c1n;
            float S0x = 0.5f * A0 * (c0k + c0n), S0y = 0.5f * A0 * (s0k - s0n);
            float S1x = 0.5f * A1 * (c1k + c1n), S1y = 0.5f * A1 * (s1k - s1n);
            sb[PIDX(pos)] = make_float2(S0x - S1y, S0y + S1x);
            sb[PIDX(pn)]  = make_float2(S0x + S1y, S1x - S0y);
        }
    }
    __syncthreads();

    // ---- Pass E (inv radix-16, contiguous) ----
    if (act) {
        float4* p4 = (float4*)(sb + 18 * ltid);
        float2 x[16];
        #pragma unroll
        for (int k = 0; k < 8; ++k) {
            float4 v = p4[k];
            x[2*k]   = make_float2(v.x, v.y);
            x[2*k+1] = make_float2(v.z, v.w);
        }
        r16_dit(x);
        #pragma unroll
        for (int k = 0; k < 8; ++k)
            p4[k] = make_float4(x[2*k].x, x[2*k].y, x[2*k+1].x, x[2*k+1].y);
    }
    __syncthreads();

    // ---- Pass F (inv radix-8, m=16) ----
    if (act) {
        #pragma unroll
        for (int it = 0; it < 2; ++it) {
            int q = ltid + it * HDIM;
            int t = q & 15;
            int d = ((q >> 4) << 7) + t;
            float2 x[8];
            #pragma unroll
            for (int j = 0; j < 8; ++j) x[j] = sb[PIDX(d + 16 * j)];
            float s, c; __sincosf(PI_F * (float)t * (1.0f/64.0f), &s, &c);
            r8_dit(x, make_float2(c, s));
            #pragma unroll
            for (int j = 0; j < 8; ++j) sb[PIDX(d + 16 * j)] = x[j];
        }
    }
    __syncthreads();

    // ---- Pass G (inv radix-8, m=128) ----
    if (act) {
        #pragma unroll
        for (int it = 0; it < 2; ++it) {
            int q = ltid + it * HDIM;
            int t = q & 127;
            int d = ((q >> 7) << 10) + t;
            float2 x[8];
            #pragma unroll
            for (int j = 0; j < 8; ++j) x[j] = sb[PIDX(d + 128 * j)];
            float s, c; __sincosf(PI_F * (float)t * (1.0f/512.0f), &s, &c);
            r8_dit(x, make_float2(c, s));
            #pragma unroll
            for (int j = 0; j < 8; ++j) sb[PIDX(d + 128 * j)] = x[j];
        }
    }
    __syncthreads();

    // ---- Pass H (inv radix-8, m=1024), scaled, back to smem ----
    if (act) {
        const float inv = 1.0f / (float)TT;
        #pragma unroll
        for (int it = 0; it < 2; ++it) {
            int q = ltid + it * HDIM;
            float2 x[8];
            #pragma unroll
            for (int j = 0; j < 8; ++j) x[j] = sb[PIDX(q + 1024 * j)];
            float s, c; __sincosf(PI_F * (float)q * (1.0f/4096.0f), &s, &c);
            r8_dit(x, make_float2(c, s));
            #pragma unroll
            for (int j = 0; j < 8; ++j)
                sb[PIDX(q + 1024 * j)] = make_float2(x[j].x * inv, x[j].y * inv);
        }
    }
    __syncthreads();

    // ---- Output: cooperative float4 store with per-channel blend ----
    const bool all4 = sel0 & sel1 & sel2 & sel3;
    for (int t = tid; t < TT; t += BDIM) {
        float2 u = buf[PIDX(t)];
        float2 v = buf[SMEMN + PIDX(t)];
        float4 o = make_float4(u.x, u.y, v.x, v.y);
        if (!all4) {
            float4 w = wrow[(size_t)t * (CC/4)];
            if (!sel0) o.x = w.x;
            if (!sel1) o.y = w.y;
            if (!sel2) o.z = w.z;
            if (!sel3) o.w = w.w;
        }
        orow[(size_t)t * (CC/4)] = o;
    }
}

extern "C" void kernel_launch(void* const* d_in, const int* in_sizes, int n_in,
                              void* d_out, int out_size)
{
    const float* wave   = (const float*)d_in[0];
    const float* phases = (const float*)d_in[1];
    const float* mask   = (const float*)d_in[2];
    float* out = (float*)d_out;

    cudaFuncSetAttribute(surrogate_kernel,
                         cudaFuncAttributeMaxDynamicSharedMemorySize, 2 * SMEMN * sizeof(float2));
    // 64 batches * 16 channel-quads = 1024 CTAs
    surrogate_kernel<<<1024, BDIM, 2 * SMEMN * sizeof(float2)>>>(wave, phases, mask, out);
}

// round 5
// speedup vs baseline: 1.1050x; 1.1050x over previous
#include <cuda_runtime.h>

#define TT 8192
#define CC 64
#define BDIM 1024
#define HDIM 512
#define LOG2T 13
// Conflict-free padding: +2 float2 per 16.
#define PIDX(i) ((i) + (((i) >> 4) << 1))
#define SMEMN (TT + ((TT >> 4) << 1))   // 9216 float2 = 72 KB per buffer

// Per-half named barrier (ids 1 and 2), 512 threads each.
#define HSYNC(h) asm volatile("bar.sync %0, %1;" :: "r"((h) + 1), "r"(HDIM) : "memory")

__device__ __forceinline__ float2 cadd(float2 a, float2 b){ return make_float2(a.x+b.x, a.y+b.y); }
__device__ __forceinline__ float2 csub(float2 a, float2 b){ return make_float2(a.x-b.x, a.y-b.y); }
__device__ __forceinline__ float2 cmulf(float2 a, float2 b){
    return make_float2(fmaf(a.x, b.x, -a.y*b.y), fmaf(a.x, b.y, a.y*b.x));
}
__device__ __forceinline__ float2 cmuli (float2 a){ return make_float2(-a.y,  a.x); }  // * i
__device__ __forceinline__ float2 cmulni(float2 a){ return make_float2( a.y, -a.x); }  // * -i

#define C45F 0.70710678118654752f
#define C8F  0.92387953251128674f
#define S8F  0.38268343236508977f
#define PI_F   3.14159265358979f
#define TWO_PI 6.28318530717959f
__device__ __forceinline__ float2 mul_psi1(float2 a){ return make_float2(C45F*(a.x+a.y), C45F*(a.y-a.x)); }
__device__ __forceinline__ float2 mul_psi3(float2 a){ return make_float2(C45F*(a.y-a.x), -C45F*(a.x+a.y)); }
__device__ __forceinline__ float2 mul_om1 (float2 a){ return make_float2(C45F*(a.x-a.y), C45F*(a.x+a.y)); }
__device__ __forceinline__ float2 mul_om3 (float2 a){ return make_float2(-C45F*(a.x+a.y), C45F*(a.x-a.y)); }

// Forward DIF radix-8 (3 fused stages), legs stride s, w1 = e^{-i pi j/(4s)}.
__device__ __forceinline__ void r8_dif(float2* x, float2 w1) {
    float2 w2 = cmulf(w1, w1), w4 = cmulf(w2, w2);
    float2 y[8];
    #pragma unroll
    for (int j = 0; j < 4; ++j) { y[j] = cadd(x[j], x[j+4]); y[j+4] = csub(x[j], x[j+4]); }
    y[4] = cmulf(y[4], w1);
    y[5] = mul_psi1(cmulf(y[5], w1));
    y[6] = cmulni (cmulf(y[6], w1));
    y[7] = mul_psi3(cmulf(y[7], w1));
    float2 z[8];
    z[0]=cadd(y[0],y[2]); z[2]=cmulf (csub(y[0],y[2]), w2);
    z[1]=cadd(y[1],y[3]); z[3]=cmulni(cmulf(csub(y[1],y[3]), w2));
    z[4]=cadd(y[4],y[6]); z[6]=cmulf (csub(y[4],y[6]), w2);
    z[5]=cadd(y[5],y[7]); z[7]=cmulni(cmulf(csub(y[5],y[7]), w2));
    x[0]=cadd(z[0],z[1]); x[1]=cmulf(csub(z[0],z[1]), w4);
    x[2]=cadd(z[2],z[3]); x[3]=cmulf(csub(z[2],z[3]), w4);
    x[4]=cadd(z[4],z[5]); x[5]=cmulf(csub(z[4],z[5]), w4);
    x[6]=cadd(z[6],z[7]); x[7]=cmulf(csub(z[6],z[7]), w4);
}

// Inverse DIT radix-8 (3 fused stages), legs stride m, v3 = e^{+i pi j/(4m)}.
__device__ __forceinline__ void r8_dit(float2* x, float2 v3) {
    float2 v2 = cmulf(v3, v3), v1 = cmulf(v2, v2);
    float2 y[8], t;
    t=cmulf(v1,x[1]); y[0]=cadd(x[0],t); y[1]=csub(x[0],t);
    t=cmulf(v1,x[3]); y[2]=cadd(x[2],t); y[3]=csub(x[2],t);
    t=cmulf(v1,x[5]); y[4]=cadd(x[4],t); y[5]=csub(x[4],t);
    t=cmulf(v1,x[7]); y[6]=cadd(x[6],t); y[7]=csub(x[6],t);
    float2 z[8];
    t=cmulf(v2,y[2]);        z[0]=cadd(y[0],t); z[2]=csub(y[0],t);
    t=cmuli(cmulf(v2,y[3])); z[1]=cadd(y[1],t); z[3]=csub(y[1],t);
    t=cmulf(v2,y[6]);        z[4]=cadd(y[4],t); z[6]=csub(y[4],t);
    t=cmuli(cmulf(v2,y[7])); z[5]=cadd(y[5],t); z[7]=csub(y[5],t);
    t=cmulf(v3,z[4]);          x[0]=cadd(z[0],t); x[4]=csub(z[0],t);
    t=mul_om1(cmulf(v3,z[5])); x[1]=cadd(z[1],t); x[5]=csub(z[1],t);
    t=cmuli  (cmulf(v3,z[6])); x[2]=cadd(z[2],t); x[6]=csub(z[2],t);
    t=mul_om3(cmulf(v3,z[7])); x[3]=cadd(z[3],t); x[7]=csub(z[3],t);
}

// Forward DIF radix-16 on 16 consecutive elements. Constant twiddles.
__device__ __forceinline__ void r16_dif(float2* x) {
    float2 y[16];
    #pragma unroll
    for (int j = 0; j < 8; ++j) { y[j] = cadd(x[j], x[j+8]); y[j+8] = csub(x[j], x[j+8]); }
    y[9]  = cmulf(y[9],  make_float2( C8F, -S8F));
    y[10] = mul_psi1(y[10]);
    y[11] = cmulf(y[11], make_float2( S8F, -C8F));
    y[12] = cmulni(y[12]);
    y[13] = cmulf(y[13], make_float2(-S8F, -C8F));
    y[14] = mul_psi3(y[14]);
    y[15] = cmulf(y[15], make_float2(-C8F, -S8F));
    float2 z[16];
    #pragma unroll
    for (int g = 0; g < 16; g += 8) {
        #pragma unroll
        for (int j = 0; j < 4; ++j) { z[g+j] = cadd(y[g+j], y[g+j+4]); z[g+j+4] = csub(y[g+j], y[g+j+4]); }
        z[g+5] = mul_psi1(z[g+5]);
        z[g+6] = cmulni (z[g+6]);
        z[g+7] = mul_psi3(z[g+7]);
    }
    float2 w[16];
    #pragma unroll
    for (int g = 0; g < 16; g += 4) {
        w[g+0]=cadd(z[g+0],z[g+2]); w[g+2]=csub(z[g+0],z[g+2]);
        w[g+1]=cadd(z[g+1],z[g+3]); w[g+3]=cmulni(csub(z[g+1],z[g+3]));
    }
    #pragma unroll
    for (int g = 0; g < 16; g += 2) { x[g] = cadd(w[g], w[g+1]); x[g+1] = csub(w[g], w[g+1]); }
}

// Inverse DIT radix-16 on 16 consecutive elements. Constant twiddles.
__device__ __forceinline__ void r16_dit(float2* x) {
    float2 y[16];
    #pragma unroll
    for (int g = 0; g < 16; g += 2) { y[g] = cadd(x[g], x[g+1]); y[g+1] = csub(x[g], x[g+1]); }
    float2 z[16];
    #pragma unroll
    for (int g = 0; g < 16; g += 4) {
        z[g+0]=cadd(y[g+0],y[g+2]); z[g+2]=csub(y[g+0],y[g+2]);
        float2 t = cmuli(y[g+3]);
        z[g+1]=cadd(y[g+1],t); z[g+3]=csub(y[g+1],t);
    }
    float2 w[16];
    #pragma unroll
    for (int g = 0; g < 16; g += 8) {
        float2 t0 = z[g+4];          w[g+0]=cadd(z[g+0],t0); w[g+4]=csub(z[g+0],t0);
        float2 t1 = mul_om1(z[g+5]); w[g+1]=cadd(z[g+1],t1); w[g+5]=csub(z[g+1],t1);
        float2 t2 = cmuli  (z[g+6]); w[g+2]=cadd(z[g+2],t2); w[g+6]=csub(z[g+2],t2);
        float2 t3 = mul_om3(z[g+7]); w[g+3]=cadd(z[g+3],t3); w[g+7]=csub(z[g+3],t3);
    }
    float2 t;
    t = w[8];                                 x[0]=cadd(w[0],t); x[8] =csub(w[0],t);
    t = cmulf(w[9],  make_float2( C8F, S8F)); x[1]=cadd(w[1],t); x[9] =csub(w[1],t);
    t = mul_om1(w[10]);                       x[2]=cadd(w[2],t); x[10]=csub(w[2],t);
    t = cmulf(w[11], make_float2( S8F, C8F)); x[3]=cadd(w[3],t); x[11]=csub(w[3],t);
    t = cmuli(w[12]);                         x[4]=cadd(w[4],t); x[12]=csub(w[4],t);
    t = cmulf(w[13], make_float2(-S8F, C8F)); x[5]=cadd(w[5],t); x[13]=csub(w[5],t);
    t = mul_om3(w[14]);                       x[6]=cadd(w[6],t); x[14]=csub(w[6],t);
    t = cmulf(w[15], make_float2(-C8F, S8F)); x[7]=cadd(w[7],t); x[15]=csub(w[7],t);
}

// Spectral update for one packed channel pair at (pos, pn), phases (phk*, phn*).
__device__ __forceinline__ void spectral_pair(float2* sb, int pos, int pn,
                                              float phkx, float phky,
                                              float phnx, float phny)
{
    float2 Zk = sb[PIDX(pos)];
    float2 Zn = sb[PIDX(pn)];
    float re0 = 0.5f * (Zk.x + Zn.x), im0 = 0.5f * (Zk.y - Zn.y);
    float re1 = 0.5f * (Zk.y + Zn.y), im1 = 0.5f * (Zn.x - Zk.x);
    float A0 = sqrtf(fmaf(re0, re0, im0 * im0));
    float A1 = sqrtf(fmaf(re1, re1, im1 * im1));
    float s0k, c0k, s0n, c0n, s1k, c1k, s1n, c1n;
    __sincosf(fmaf(phkx, TWO_PI, -PI_F), &s0k, &c0k); s0k = -s0k; c0k = -c0k;
    __sincosf(fmaf(phnx, TWO_PI, -PI_F), &s0n, &c0n); s0n = -s0n; c0n = -c0n;
    __sincosf(fmaf(phky, TWO_PI, -PI_F), &s1k, &c1k); s1k = -s1k; c1k = -c1k;
    __sincosf(fmaf(phny, TWO_PI, -PI_F), &s1n, &c1n); s1n = -s1n; c1n = -c1n;
    float S0x = 0.5f * A0 * (c0k + c0n), S0y = 0.5f * A0 * (s0k - s0n);
    float S1x = 0.5f * A1 * (c1k + c1n), S1y = 0.5f * A1 * (s1k - s1n);
    sb[PIDX(pos)] = make_float2(S0x - S1y, S0y + S1x);
    sb[PIDX(pn)]  = make_float2(S0x + S1y, S1x - S0y);
}

__global__ void __launch_bounds__(BDIM, 1)
surrogate_kernel(const float* __restrict__ wave,
                 const float* __restrict__ phases,
                 const float* __restrict__ mask,
                 float* __restrict__ out)
{
    extern __shared__ float2 buf[];   // 2 * SMEMN float2 = 144 KB
    const int tid = threadIdx.x;
    const int blk = blockIdx.x;
    const int b  = blk >> 4;          // 16 channel-quads per batch
    const int c0 = (blk & 15) * 4;    // 4 channels per CTA

    const bool sel0 = mask[b * CC + c0 + 0] < 0.5f;
    const bool sel1 = mask[b * CC + c0 + 1] < 0.5f;
    const bool sel2 = mask[b * CC + c0 + 2] < 0.5f;
    const bool sel3 = mask[b * CC + c0 + 3] < 0.5f;

    const float4* wrow = (const float4*)(wave + ((size_t)b * TT) * CC + c0);
    float4*       orow = (float4*)      (out  + ((size_t)b * TT) * CC + c0);

    // No channel selected: pure float4 copy.
    if (!(sel0 | sel1 | sel2 | sel3)) {
        for (int t = tid; t < TT; t += BDIM)
            orow[(size_t)t * (CC/4)] = wrow[(size_t)t * (CC/4)];
        return;
    }

    // ---- Staging: cooperative float4 load -> two complex buffers ----
    for (int t = tid; t < TT; t += BDIM) {
        float4 v = wrow[(size_t)t * (CC/4)];
        buf[PIDX(t)]         = make_float2(v.x, v.y);
        buf[SMEMN + PIDX(t)] = make_float2(v.z, v.w);
    }
    __syncthreads();

    const int half = tid >> 9;        // 0: channels c0,c0+1; 1: channels c0+2,c0+3
    const int ltid = tid & (HDIM - 1);
    float2* sb = buf + half * SMEMN;
    const bool act = half ? (sel2 | sel3) : (sel0 | sel1);

    // ---- Pass A (fwd radix-8, s=1024) ----
    if (act) {
        #pragma unroll
        for (int it = 0; it < 2; ++it) {
            int q = ltid + it * HDIM;
            float2 x[8];
            #pragma unroll
            for (int j = 0; j < 8; ++j) x[j] = sb[PIDX(q + 1024 * j)];
            float s, c; __sincosf(-PI_F * (float)q * (1.0f/4096.0f), &s, &c);
            r8_dif(x, make_float2(c, s));
            #pragma unroll
            for (int j = 0; j < 8; ++j) sb[PIDX(q + 1024 * j)] = x[j];
        }
    }
    HSYNC(half);

    // ---- Pass B (fwd radix-8, s=128) ----
    if (act) {
        #pragma unroll
        for (int it = 0; it < 2; ++it) {
            int q = ltid + it * HDIM;
            int t = q & 127;
            int d = ((q >> 7) << 10) + t;
            float2 x[8];
            #pragma unroll
            for (int j = 0; j < 8; ++j) x[j] = sb[PIDX(d + 128 * j)];
            float s, c; __sincosf(-PI_F * (float)t * (1.0f/512.0f), &s, &c);
            r8_dif(x, make_float2(c, s));
            #pragma unroll
            for (int j = 0; j < 8; ++j) sb[PIDX(d + 128 * j)] = x[j];
        }
    }
    HSYNC(half);

    // ---- Pass C (fwd radix-8, s=16) ----
    if (act) {
        #pragma unroll
        for (int it = 0; it < 2; ++it) {
            int q = ltid + it * HDIM;
            int t = q & 15;
            int d = ((q >> 4) << 7) + t;
            float2 x[8];
            #pragma unroll
            for (int j = 0; j < 8; ++j) x[j] = sb[PIDX(d + 16 * j)];
            float s, c; __sincosf(-PI_F * (float)t * (1.0f/64.0f), &s, &c);
            r8_dif(x, make_float2(c, s));
            #pragma unroll
            for (int j = 0; j < 8; ++j) sb[PIDX(d + 16 * j)] = x[j];
        }
    }
    HSYNC(half);

    // ---- Pass D (fwd radix-16, contiguous) ----
    if (act) {
        float4* p4 = (float4*)(sb + 18 * ltid);
        float2 x[16];
        #pragma unroll
        for (int k = 0; k < 8; ++k) {
            float4 v = p4[k];
            x[2*k]   = make_float2(v.x, v.y);
            x[2*k+1] = make_float2(v.z, v.w);
        }
        r16_dif(x);
        #pragma unroll
        for (int k = 0; k < 8; ++k)
            p4[k] = make_float4(x[2*k].x, x[2*k].y, x[2*k+1].x, x[2*k+1].y);
    }
    __syncthreads();   // join: spectral touches both buffers

    // ---- Spectral stage: all 1024 threads, both buffers, float4 phases ----
    {
        const float* pb = phases + ((size_t)b * TT) * CC + c0;
        #pragma unroll
        for (int it = 0; it < 8; ++it) {
            int pos = tid + it * BDIM;
            int k = __brev(pos) >> (32 - LOG2T);
            if (k > TT / 2) continue;
            int kn = (TT - k) & (TT - 1);
            int pn = __brev(kn) >> (32 - LOG2T);
            float4 Pk = *(const float4*)(pb + (size_t)k  * CC);
            float4 Pn = *(const float4*)(pb + (size_t)kn * CC);
            spectral_pair(buf,         pos, pn, Pk.x, Pk.y, Pn.x, Pn.y);
            spectral_pair(buf + SMEMN, pos, pn, Pk.z, Pk.w, Pn.z, Pn.w);
        }
    }
    __syncthreads();   // join: halves resume private work

    // ---- Pass E (inv radix-16, contiguous) ----
    if (act) {
        float4* p4 = (float4*)(sb + 18 * ltid);
        float2 x[16];
        #pragma unroll
        for (int k = 0; k < 8; ++k) {
            float4 v = p4[k];
            x[2*k]   = make_float2(v.x, v.y);
            x[2*k+1] = make_float2(v.z, v.w);
        }
        r16_dit(x);
        #pragma unroll
        for (int k = 0; k < 8; ++k)
            p4[k] = make_float4(x[2*k].x, x[2*k].y, x[2*k+1].x, x[2*k+1].y);
    }
    HSYNC(half);

    // ---- Pass F (inv radix-8, m=16) ----
    if (act) {
        #pragma unroll
        for (int it = 0; it < 2; ++it) {
            int q = ltid + it * HDIM;
            int t = q & 15;
            int d = ((q >> 4) << 7) + t;
            float2 x[8];
            #pragma unroll
            for (int j = 0; j < 8; ++j) x[j] = sb[PIDX(d + 16 * j)];
            float s, c; __sincosf(PI_F * (float)t * (1.0f/64.0f), &s, &c);
            r8_dit(x, make_float2(c, s));
            #pragma unroll
            for (int j = 0; j < 8; ++j) sb[PIDX(d + 16 * j)] = x[j];
        }
    }
    HSYNC(half);

    // ---- Pass G (inv radix-8, m=128) ----
    if (act) {
        #pragma unroll
        for (int it = 0; it < 2; ++it) {
            int q = ltid + it * HDIM;
            int t = q & 127;
            int d = ((q >> 7) << 10) + t;
            float2 x[8];
            #pragma unroll
            for (int j = 0; j < 8; ++j) x[j] = sb[PIDX(d + 128 * j)];
            float s, c; __sincosf(PI_F * (float)t * (1.0f/512.0f), &s, &c);
            r8_dit(x, make_float2(c, s));
            #pragma unroll
            for (int j = 0; j < 8; ++j) sb[PIDX(d + 128 * j)] = x[j];
        }
    }
    HSYNC(half);

    // ---- Pass H (inv radix-8, m=1024), scaled, back to smem ----
    if (act) {
        const float inv = 1.0f / (float)TT;
        #pragma unroll
        for (int it = 0; it < 2; ++it) {
            int q = ltid + it * HDIM;
            float2 x[8];
            #pragma unroll
            for (int j = 0; j < 8; ++j) x[j] = sb[PIDX(q + 1024 * j)];
            float s, c; __sincosf(PI_F * (float)q * (1.0f/4096.0f), &s, &c);
            r8_dit(x, make_float2(c, s));
            #pragma unroll
            for (int j = 0; j < 8; ++j)
                sb[PIDX(q + 1024 * j)] = make_float2(x[j].x * inv, x[j].y * inv);
        }
    }
    __syncthreads();   // join: output reads both buffers

    // ---- Output: cooperative float4 store with per-channel blend ----
    const bool all4 = sel0 & sel1 & sel2 & sel3;
    for (int t = tid; t < TT; t += BDIM) {
        float2 u = buf[PIDX(t)];
        float2 v = buf[SMEMN + PIDX(t)];
        float4 o = make_float4(u.x, u.y, v.x, v.y);
        if (!all4) {
            float4 w = wrow[(size_t)t * (CC/4)];
            if (!sel0) o.x = w.x;
            if (!sel1) o.y = w.y;
            if (!sel2) o.z = w.z;
            if (!sel3) o.w = w.w;
        }
        orow[(size_t)t * (CC/4)] = o;
    }
}

extern "C" void kernel_launch(void* const* d_in, const int* in_sizes, int n_in,
                              void* d_out, int out_size)
{
    const float* wave   = (const float*)d_in[0];
    const float* phases = (const float*)d_in[1];
    const float* mask   = (const float*)d_in[2];
    float* out = (float*)d_out;

    cudaFuncSetAttribute(surrogate_kernel,
                         cudaFuncAttributeMaxDynamicSharedMemorySize, 2 * SMEMN * sizeof(float2));
    surrogate_kernel<<<1024, BDIM, 2 * SMEMN * sizeof(float2)>>>(wave, phases, mask, out);
}

// round 6
// speedup vs baseline: 1.1320x; 1.0244x over previous
#include <cuda_runtime.h>
#include <cuda.h>

#define TT 8192
#define CC 64
#define BDIM 1024
#define HDIM 512
#define LOG2T 13
// Conflict-free padding: +2 float2 per 16.
#define PIDX(i) ((i) + (((i) >> 4) << 1))
#define SMEMN (TT + ((TT >> 4) << 1))   // 9216 float2 = 72 KB per buffer

#define CHUNK 1024
#define NCHUNK (TT / CHUNK)             // 8
#define TILE_BYTES (CHUNK * 16)         // 16 KB

// smem byte offsets
#define OFF_BARS  0
#define OFF_TILE0 1024
#define OFF_TILE1 (OFF_TILE0 + TILE_BYTES)
#define OFF_TW0   (OFF_TILE1 + TILE_BYTES)
#define OFF_TW1   (OFF_TW0 + TILE_BYTES)
#define OFF_BUF   (OFF_TW1 + TILE_BYTES)          // 66560
#define SMEM_TOTAL (OFF_BUF + 2 * SMEMN * 8)      // 66560 + 147456 = 214016

// Per-half named barrier (ids 1 and 2), 512 threads each.
#define HSYNC(h) asm volatile("bar.sync %0, %1;" :: "r"((h) + 1), "r"(HDIM) : "memory")

__device__ __forceinline__ uint32_t smem_u32(const void* p) {
    uint32_t a;
    asm("{ .reg .u64 t; cvta.to.shared.u64 t, %1; cvt.u32.u64 %0, t; }" : "=r"(a) : "l"(p));
    return a;
}
__device__ __forceinline__ void mbar_init(uint32_t a, uint32_t cnt) {
    asm volatile("mbarrier.init.shared.b64 [%0], %1;" :: "r"(a), "r"(cnt) : "memory");
}
__device__ __forceinline__ void mbar_expect_tx(uint32_t a, uint32_t bytes) {
    asm volatile("mbarrier.arrive.expect_tx.shared.b64 _, [%0], %1;" :: "r"(a), "r"(bytes) : "memory");
}
__device__ __forceinline__ void mbar_wait(uint32_t a, uint32_t parity) {
    asm volatile(
        "{\n\t.reg .pred P;\n\t"
        "WL_%=:\n\t"
        "mbarrier.try_wait.parity.acquire.cta.shared::cta.b64 P, [%0], %1, 0x989680;\n\t"
        "@P bra.uni WD_%=;\n\t"
        "bra.uni WL_%=;\n\t"
        "WD_%=:\n\t}"
        :: "r"(a), "r"(parity) : "memory");
}
__device__ __forceinline__ void tma_load3d(uint32_t dst, const CUtensorMap* m,
                                           int cx, int cy, int cz, uint32_t bar) {
    asm volatile(
        "cp.async.bulk.tensor.3d.shared::cta.global.tile.mbarrier::complete_tx::bytes "
        "[%0], [%1, {%2, %3, %4}], [%5];"
        :: "r"(dst), "l"(m), "r"(cx), "r"(cy), "r"(cz), "r"(bar) : "memory");
}
__device__ __forceinline__ void tma_store3d(const CUtensorMap* m,
                                            int cx, int cy, int cz, uint32_t src) {
    asm volatile(
        "cp.async.bulk.tensor.3d.global.shared::cta.tile.bulk_group "
        "[%0, {%1, %2, %3}], [%4];"
        :: "l"(m), "r"(cx), "r"(cy), "r"(cz), "r"(src) : "memory");
}
#define TMA_COMMIT() asm volatile("cp.async.bulk.commit_group;" ::: "memory")
#define TMA_WAIT(n)  asm volatile("cp.async.bulk.wait_group %0;" :: "n"(n) : "memory")
#define FENCE_ASYNC() asm volatile("fence.proxy.async;" ::: "memory")

__device__ __forceinline__ float2 cadd(float2 a, float2 b){ return make_float2(a.x+b.x, a.y+b.y); }
__device__ __forceinline__ float2 csub(float2 a, float2 b){ return make_float2(a.x-b.x, a.y-b.y); }
__device__ __forceinline__ float2 cmulf(float2 a, float2 b){
    return make_float2(fmaf(a.x, b.x, -a.y*b.y), fmaf(a.x, b.y, a.y*b.x));
}
__device__ __forceinline__ float2 cmuli (float2 a){ return make_float2(-a.y,  a.x); }
__device__ __forceinline__ float2 cmulni(float2 a){ return make_float2( a.y, -a.x); }

#define C45F 0.70710678118654752f
#define C8F  0.92387953251128674f
#define S8F  0.38268343236508977f
#define PI_F   3.14159265358979f
#define TWO_PI 6.28318530717959f
__device__ __forceinline__ float2 mul_psi1(float2 a){ return make_float2(C45F*(a.x+a.y), C45F*(a.y-a.x)); }
__device__ __forceinline__ float2 mul_psi3(float2 a){ return make_float2(C45F*(a.y-a.x), -C45F*(a.x+a.y)); }
__device__ __forceinline__ float2 mul_om1 (float2 a){ return make_float2(C45F*(a.x-a.y), C45F*(a.x+a.y)); }
__device__ __forceinline__ float2 mul_om3 (float2 a){ return make_float2(-C45F*(a.x+a.y), C45F*(a.x-a.y)); }

__device__ __forceinline__ void r8_dif(float2* x, float2 w1) {
    float2 w2 = cmulf(w1, w1), w4 = cmulf(w2, w2);
    float2 y[8];
    #pragma unroll
    for (int j = 0; j < 4; ++j) { y[j] = cadd(x[j], x[j+4]); y[j+4] = csub(x[j], x[j+4]); }
    y[4] = cmulf(y[4], w1);
    y[5] = mul_psi1(cmulf(y[5], w1));
    y[6] = cmulni (cmulf(y[6], w1));
    y[7] = mul_psi3(cmulf(y[7], w1));
    float2 z[8];
    z[0]=cadd(y[0],y[2]); z[2]=cmulf (csub(y[0],y[2]), w2);
    z[1]=cadd(y[1],y[3]); z[3]=cmulni(cmulf(csub(y[1],y[3]), w2));
    z[4]=cadd(y[4],y[6]); z[6]=cmulf (csub(y[4],y[6]), w2);
    z[5]=cadd(y[5],y[7]); z[7]=cmulni(cmulf(csub(y[5],y[7]), w2));
    x[0]=cadd(z[0],z[1]); x[1]=cmulf(csub(z[0],z[1]), w4);
    x[2]=cadd(z[2],z[3]); x[3]=cmulf(csub(z[2],z[3]), w4);
    x[4]=cadd(z[4],z[5]); x[5]=cmulf(csub(z[4],z[5]), w4);
    x[6]=cadd(z[6],z[7]); x[7]=cmulf(csub(z[6],z[7]), w4);
}

__device__ __forceinline__ void r8_dit(float2* x, float2 v3) {
    float2 v2 = cmulf(v3, v3), v1 = cmulf(v2, v2);
    float2 y[8], t;
    t=cmulf(v1,x[1]); y[0]=cadd(x[0],t); y[1]=csub(x[0],t);
    t=cmulf(v1,x[3]); y[2]=cadd(x[2],t); y[3]=csub(x[2],t);
    t=cmulf(v1,x[5]); y[4]=cadd(x[4],t); y[5]=csub(x[4],t);
    t=cmulf(v1,x[7]); y[6]=cadd(x[6],t); y[7]=csub(x[6],t);
    float2 z[8];
    t=cmulf(v2,y[2]);        z[0]=cadd(y[0],t); z[2]=csub(y[0],t);
    t=cmuli(cmulf(v2,y[3])); z[1]=cadd(y[1],t); z[3]=csub(y[1],t);
    t=cmulf(v2,y[6]);        z[4]=cadd(y[4],t); z[6]=csub(y[4],t);
    t=cmuli(cmulf(v2,y[7])); z[5]=cadd(y[5],t); z[7]=csub(y[5],t);
    t=cmulf(v3,z[4]);          x[0]=cadd(z[0],t); x[4]=csub(z[0],t);
    t=mul_om1(cmulf(v3,z[5])); x[1]=cadd(z[1],t); x[5]=csub(z[1],t);
    t=cmuli  (cmulf(v3,z[6])); x[2]=cadd(z[2],t); x[6]=csub(z[2],t);
    t=mul_om3(cmulf(v3,z[7])); x[3]=cadd(z[3],t); x[7]=csub(z[3],t);
}

__device__ __forceinline__ void r16_dif(float2* x) {
    float2 y[16];
    #pragma unroll
    for (int j = 0; j < 8; ++j) { y[j] = cadd(x[j], x[j+8]); y[j+8] = csub(x[j], x[j+8]); }
    y[9]  = cmulf(y[9],  make_float2( C8F, -S8F));
    y[10] = mul_psi1(y[10]);
    y[11] = cmulf(y[11], make_float2( S8F, -C8F));
    y[12] = cmulni(y[12]);
    y[13] = cmulf(y[13], make_float2(-S8F, -C8F));
    y[14] = mul_psi3(y[14]);
    y[15] = cmulf(y[15], make_float2(-C8F, -S8F));
    float2 z[16];
    #pragma unroll
    for (int g = 0; g < 16; g += 8) {
        #pragma unroll
        for (int j = 0; j < 4; ++j) { z[g+j] = cadd(y[g+j], y[g+j+4]); z[g+j+4] = csub(y[g+j], y[g+j+4]); }
        z[g+5] = mul_psi1(z[g+5]);
        z[g+6] = cmulni (z[g+6]);
        z[g+7] = mul_psi3(z[g+7]);
    }
    float2 w[16];
    #pragma unroll
    for (int g = 0; g < 16; g += 4) {
        w[g+0]=cadd(z[g+0],z[g+2]); w[g+2]=csub(z[g+0],z[g+2]);
        w[g+1]=cadd(z[g+1],z[g+3]); w[g+3]=cmulni(csub(z[g+1],z[g+3]));
    }
    #pragma unroll
    for (int g = 0; g < 16; g += 2) { x[g] = cadd(w[g], w[g+1]); x[g+1] = csub(w[g], w[g+1]); }
}

__device__ __forceinline__ void r16_dit(float2* x) {
    float2 y[16];
    #pragma unroll
    for (int g = 0; g < 16; g += 2) { y[g] = cadd(x[g], x[g+1]); y[g+1] = csub(x[g], x[g+1]); }
    float2 z[16];
    #pragma unroll
    for (int g = 0; g < 16; g += 4) {
        z[g+0]=cadd(y[g+0],y[g+2]); z[g+2]=csub(y[g+0],y[g+2]);
        float2 t = cmuli(y[g+3]);
        z[g+1]=cadd(y[g+1],t); z[g+3]=csub(y[g+1],t);
    }
    float2 w[16];
    #pragma unroll
    for (int g = 0; g < 16; g += 8) {
        float2 t0 = z[g+4];          w[g+0]=cadd(z[g+0],t0); w[g+4]=csub(z[g+0],t0);
        float2 t1 = mul_om1(z[g+5]); w[g+1]=cadd(z[g+1],t1); w[g+5]=csub(z[g+1],t1);
        float2 t2 = cmuli  (z[g+6]); w[g+2]=cadd(z[g+2],t2); w[g+6]=csub(z[g+2],t2);
        float2 t3 = mul_om3(z[g+7]); w[g+3]=cadd(z[g+3],t3); w[g+7]=csub(z[g+3],t3);
    }
    float2 t;
    t = w[8];                                 x[0]=cadd(w[0],t); x[8] =csub(w[0],t);
    t = cmulf(w[9],  make_float2( C8F, S8F)); x[1]=cadd(w[1],t); x[9] =csub(w[1],t);
    t = mul_om1(w[10]);                       x[2]=cadd(w[2],t); x[10]=csub(w[2],t);
    t = cmulf(w[11], make_float2( S8F, C8F)); x[3]=cadd(w[3],t); x[11]=csub(w[3],t);
    t = cmuli(w[12]);                         x[4]=cadd(w[4],t); x[12]=csub(w[4],t);
    t = cmulf(w[13], make_float2(-S8F, C8F)); x[5]=cadd(w[5],t); x[13]=csub(w[5],t);
    t = mul_om3(w[14]);                       x[6]=cadd(w[6],t); x[14]=csub(w[6],t);
    t = cmulf(w[15], make_float2(-C8F, S8F)); x[7]=cadd(w[7],t); x[15]=csub(w[7],t);
}

__device__ __forceinline__ void spectral_pair(float2* sb, int pos, int pn,
                                              float phkx, float phky,
                                              float phnx, float phny)
{
    float2 Zk = sb[PIDX(pos)];
    float2 Zn = sb[PIDX(pn)];
    float re0 = 0.5f * (Zk.x + Zn.x), im0 = 0.5f * (Zk.y - Zn.y);
    float re1 = 0.5f * (Zk.y + Zn.y), im1 = 0.5f * (Zn.x - Zk.x);
    float A0 = sqrtf(fmaf(re0, re0, im0 * im0));
    float A1 = sqrtf(fmaf(re1, re1, im1 * im1));
    float s0k, c0k, s0n, c0n, s1k, c1k, s1n, c1n;
    __sincosf(fmaf(phkx, TWO_PI, -PI_F), &s0k, &c0k); s0k = -s0k; c0k = -c0k;
    __sincosf(fmaf(phnx, TWO_PI, -PI_F), &s0n, &c0n); s0n = -s0n; c0n = -c0n;
    __sincosf(fmaf(phky, TWO_PI, -PI_F), &s1k, &c1k); s1k = -s1k; c1k = -c1k;
    __sincosf(fmaf(phny, TWO_PI, -PI_F), &s1n, &c1n); s1n = -s1n; c1n = -c1n;
    float S0x = 0.5f * A0 * (c0k + c0n), S0y = 0.5f * A0 * (s0k - s0n);
    float S1x = 0.5f * A1 * (c1k + c1n), S1y = 0.5f * A1 * (s1k - s1n);
    sb[PIDX(pos)] = make_float2(S0x - S1y, S0y + S1x);
    sb[PIDX(pn)]  = make_float2(S0x + S1y, S1x - S0y);
}

__global__ void __launch_bounds__(BDIM, 1)
surrogate_kernel(const float* __restrict__ wave,
                 const float* __restrict__ phases,
                 const float* __restrict__ mask,
                 float* __restrict__ out,
                 const __grid_constant__ CUtensorMap mapW,
                 const __grid_constant__ CUtensorMap mapO)
{
    extern __shared__ __align__(1024) char smem[];
    float4* tile[2]  = { (float4*)(smem + OFF_TILE0), (float4*)(smem + OFF_TILE1) };
    float4* tileW[2] = { (float4*)(smem + OFF_TW0),   (float4*)(smem + OFF_TW1) };
    float2* buf  = (float2*)(smem + OFF_BUF);
    const uint32_t barBase = smem_u32(smem + OFF_BARS);   // full0,full1,fullW0,fullW1 (8B each)

    const int tid = threadIdx.x;
    const int blk = blockIdx.x;
    const int b  = blk >> 4;
    const int c0 = (blk & 15) * 4;

    const bool sel0 = mask[b * CC + c0 + 0] < 0.5f;
    const bool sel1 = mask[b * CC + c0 + 1] < 0.5f;
    const bool sel2 = mask[b * CC + c0 + 2] < 0.5f;
    const bool sel3 = mask[b * CC + c0 + 3] < 0.5f;

    const float4* wrow = (const float4*)(wave + ((size_t)b * TT) * CC + c0);
    float4*       orow = (float4*)      (out  + ((size_t)b * TT) * CC + c0);

    // No channel selected: pure float4 copy (6.25% of CTAs).
    if (!(sel0 | sel1 | sel2 | sel3)) {
        for (int t = tid; t < TT; t += BDIM)
            orow[(size_t)t * (CC/4)] = wrow[(size_t)t * (CC/4)];
        return;
    }

    // ---- Init mbarriers ----
    if (tid == 0) {
        #pragma unroll
        for (int i = 0; i < 4; ++i) mbar_init(barBase + 8 * i, 1);
    }
    __syncthreads();

    // ---- Input: TMA-staged chunks, double buffered ----
    if (tid == 0) {
        #pragma unroll
        for (int c = 0; c < 2; ++c) {
            mbar_expect_tx(barBase + 8 * c, TILE_BYTES);
            #pragma unroll
            for (int s = 0; s < 4; ++s)
                tma_load3d(smem_u32(tile[c]) + s * 4096, &mapW, c0, c * CHUNK + s * 256, b,
                           barBase + 8 * c);
        }
    }
    for (int ch = 0; ch < NCHUNK; ++ch) {
        int slot = ch & 1;
        mbar_wait(barBase + 8 * slot, (ch >> 1) & 1);
        float4 v = tile[slot][tid];
        int t = ch * CHUNK + tid;
        buf[PIDX(t)]         = make_float2(v.x, v.y);
        buf[SMEMN + PIDX(t)] = make_float2(v.z, v.w);
        __syncthreads();
        if (tid == 0 && ch + 2 < NCHUNK) {
            mbar_expect_tx(barBase + 8 * slot, TILE_BYTES);
            #pragma unroll
            for (int s = 0; s < 4; ++s)
                tma_load3d(smem_u32(tile[slot]) + s * 4096, &mapW, c0,
                           (ch + 2) * CHUNK + s * 256, b, barBase + 8 * slot);
        }
    }

    const int half = tid >> 9;
    const int ltid = tid & (HDIM - 1);
    float2* sb = buf + half * SMEMN;
    const bool act = half ? (sel2 | sel3) : (sel0 | sel1);

    // ---- Pass A (fwd radix-8, s=1024) ----
    if (act) {
        #pragma unroll
        for (int it = 0; it < 2; ++it) {
            int q = ltid + it * HDIM;
            float2 x[8];
            #pragma unroll
            for (int j = 0; j < 8; ++j) x[j] = sb[PIDX(q + 1024 * j)];
            float s, c; __sincosf(-PI_F * (float)q * (1.0f/4096.0f), &s, &c);
            r8_dif(x, make_float2(c, s));
            #pragma unroll
            for (int j = 0; j < 8; ++j) sb[PIDX(q + 1024 * j)] = x[j];
        }
    }
    HSYNC(half);

    // ---- Pass B (fwd radix-8, s=128) ----
    if (act) {
        #pragma unroll
        for (int it = 0; it < 2; ++it) {
            int q = ltid + it * HDIM;
            int t = q & 127;
            int d = ((q >> 7) << 10) + t;
            float2 x[8];
            #pragma unroll
            for (int j = 0; j < 8; ++j) x[j] = sb[PIDX(d + 128 * j)];
            float s, c; __sincosf(-PI_F * (float)t * (1.0f/512.0f), &s, &c);
            r8_dif(x, make_float2(c, s));
            #pragma unroll
            for (int j = 0; j < 8; ++j) sb[PIDX(d + 128 * j)] = x[j];
        }
    }
    HSYNC(half);

    // ---- Pass C (fwd radix-8, s=16) ----
    if (act) {
        #pragma unroll
        for (int it = 0; it < 2; ++it) {
            int q = ltid + it * HDIM;
            int t = q & 15;
            int d = ((q >> 4) << 7) + t;
            float2 x[8];
            #pragma unroll
            for (int j = 0; j < 8; ++j) x[j] = sb[PIDX(d + 16 * j)];
            float s, c; __sincosf(-PI_F * (float)t * (1.0f/64.0f), &s, &c);
            r8_dif(x, make_float2(c, s));
            #pragma unroll
            for (int j = 0; j < 8; ++j) sb[PIDX(d + 16 * j)] = x[j];
        }
    }
    HSYNC(half);

    // ---- Pass D (fwd radix-16, contiguous) ----
    if (act) {
        float4* p4 = (float4*)(sb + 18 * ltid);
        float2 x[16];
        #pragma unroll
        for (int k = 0; k < 8; ++k) {
            float4 v = p4[k];
            x[2*k]   = make_float2(v.x, v.y);
            x[2*k+1] = make_float2(v.z, v.w);
        }
        r16_dif(x);
        #pragma unroll
        for (int k = 0; k < 8; ++k)
            p4[k] = make_float4(x[2*k].x, x[2*k].y, x[2*k+1].x, x[2*k+1].y);
    }
    __syncthreads();

    // ---- Spectral stage: all 1024 threads, both buffers, float4 phases ----
    {
        const float* pb = phases + ((size_t)b * TT) * CC + c0;
        #pragma unroll
        for (int it = 0; it < 8; ++it) {
            int pos = tid + it * BDIM;
            int k = __brev(pos) >> (32 - LOG2T);
            if (k > TT / 2) continue;
            int kn = (TT - k) & (TT - 1);
            int pn = __brev(kn) >> (32 - LOG2T);
            float4 Pk = *(const float4*)(pb + (size_t)k  * CC);
            float4 Pn = *(const float4*)(pb + (size_t)kn * CC);
            spectral_pair(buf,         pos, pn, Pk.x, Pk.y, Pn.x, Pn.y);
            spectral_pair(buf + SMEMN, pos, pn, Pk.z, Pk.w, Pn.z, Pn.w);
        }
    }
    __syncthreads();

    // ---- Pass E (inv radix-16, contiguous) ----
    if (act) {
        float4* p4 = (float4*)(sb + 18 * ltid);
        float2 x[16];
        #pragma unroll
        for (int k = 0; k < 8; ++k) {
            float4 v = p4[k];
            x[2*k]   = make_float2(v.x, v.y);
            x[2*k+1] = make_float2(v.z, v.w);
        }
        r16_dit(x);
        #pragma unroll
        for (int k = 0; k < 8; ++k)
            p4[k] = make_float4(x[2*k].x, x[2*k].y, x[2*k+1].x, x[2*k+1].y);
    }
    HSYNC(half);

    // ---- Pass F (inv radix-8, m=16) ----
    if (act) {
        #pragma unroll
        for (int it = 0; it < 2; ++it) {
            int q = ltid + it * HDIM;
            int t = q & 15;
            int d = ((q >> 4) << 7) + t;
            float2 x[8];
            #pragma unroll
            for (int j = 0; j < 8; ++j) x[j] = sb[PIDX(d + 16 * j)];
            float s, c; __sincosf(PI_F * (float)t * (1.0f/64.0f), &s, &c);
            r8_dit(x, make_float2(c, s));
            #pragma unroll
            for (int j = 0; j < 8; ++j) sb[PIDX(d + 16 * j)] = x[j];
        }
    }
    HSYNC(half);

    // ---- Pass G (inv radix-8, m=128) ----
    if (act) {
        #pragma unroll
        for (int it = 0; it < 2; ++it) {
            int q = ltid + it * HDIM;
            int t = q & 127;
            int d = ((q >> 7) << 10) + t;
            float2 x[8];
            #pragma unroll
            for (int j = 0; j < 8; ++j) x[j] = sb[PIDX(d + 128 * j)];
            float s, c; __sincosf(PI_F * (float)t * (1.0f/512.0f), &s, &c);
            r8_dit(x, make_float2(c, s));
            #pragma unroll
            for (int j = 0; j < 8; ++j) sb[PIDX(d + 128 * j)] = x[j];
        }
    }
    HSYNC(half);

    // ---- Pass H (inv radix-8, m=1024), scaled, back to smem ----
    if (act) {
        const float inv = 1.0f / (float)TT;
        #pragma unroll
        for (int it = 0; it < 2; ++it) {
            int q = ltid + it * HDIM;
            float2 x[8];
            #pragma unroll
            for (int j = 0; j < 8; ++j) x[j] = sb[PIDX(q + 1024 * j)];
            float s, c; __sincosf(PI_F * (float)q * (1.0f/4096.0f), &s, &c);
            r8_dit(x, make_float2(c, s));
            #pragma unroll
            for (int j = 0; j < 8; ++j)
                sb[PIDX(q + 1024 * j)] = make_float2(x[j].x * inv, x[j].y * inv);
        }
    }
    __syncthreads();

    // ---- Output: pack chunks + TMA store, blend via TMA-prefetched wave chunks ----
    const bool blend = !(sel0 & sel1 & sel2 & sel3);
    if (tid == 0 && blend) {
        #pragma unroll
        for (int c = 0; c < 2; ++c) {
            mbar_expect_tx(barBase + 16 + 8 * c, TILE_BYTES);
            #pragma unroll
            for (int s = 0; s < 4; ++s)
                tma_load3d(smem_u32(tileW[c]) + s * 4096, &mapW, c0, c * CHUNK + s * 256, b,
                           barBase + 16 + 8 * c);
        }
    }
    for (int ch = 0; ch < NCHUNK; ++ch) {
        int slot = ch & 1;
        if (blend) mbar_wait(barBase + 16 + 8 * slot, (ch >> 1) & 1);
        if (tid == 0 && ch >= 2) TMA_WAIT(1);   // pack slot from ch-2 reusable
        __syncthreads();
        int t = ch * CHUNK + tid;
        float2 u = buf[PIDX(t)];
        float2 v = buf[SMEMN + PIDX(t)];
        float4 o = make_float4(u.x, u.y, v.x, v.y);
        if (blend) {
            float4 w = tileW[slot][tid];
            if (!sel0) o.x = w.x;
            if (!sel1) o.y = w.y;
            if (!sel2) o.z = w.z;
            if (!sel3) o.w = w.w;
        }
        tile[slot][tid] = o;
        __syncthreads();
        if (tid == 0) {
            FENCE_ASYNC();
            #pragma unroll
            for (int s = 0; s < 4; ++s)
                tma_store3d(&mapO, c0, ch * CHUNK + s * 256, b,
                            smem_u32(tile[slot]) + s * 4096);
            TMA_COMMIT();
            if (blend && ch + 2 < NCHUNK) {
                mbar_expect_tx(barBase + 16 + 8 * slot, TILE_BYTES);
                #pragma unroll
                for (int s = 0; s < 4; ++s)
                    tma_load3d(smem_u32(tileW[slot]) + s * 4096, &mapW, c0,
                               (ch + 2) * CHUNK + s * 256, b, barBase + 16 + 8 * slot);
            }
        }
    }
    if (tid == 0) TMA_WAIT(0);
}

// ---- Host side ----
typedef CUresult (*EncodeFn)(CUtensorMap*, CUtensorMapDataType, cuuint32_t, void*,
                             const cuuint64_t*, const cuuint64_t*, const cuuint32_t*,
                             const cuuint32_t*, CUtensorMapInterleave, CUtensorMapSwizzle,
                             CUtensorMapL2promotion, CUtensorMapFloatOOBfill);

static void make_map(EncodeFn enc, CUtensorMap* m, void* base) {
    cuuint64_t dims[3]    = { CC, TT, 64 };
    cuuint64_t strides[2] = { (cuuint64_t)CC * 4, (cuuint64_t)TT * CC * 4 };
    cuuint32_t box[3]     = { 4, 256, 1 };
    cuuint32_t es[3]      = { 1, 1, 1 };
    enc(m, CU_TENSOR_MAP_DATA_TYPE_FLOAT32, 3, base, dims, strides, box, es,
        CU_TENSOR_MAP_INTERLEAVE_NONE, CU_TENSOR_MAP_SWIZZLE_NONE,
        CU_TENSOR_MAP_L2_PROMOTION_L2_128B, CU_TENSOR_MAP_FLOAT_OOB_FILL_NONE);
}

extern "C" void kernel_launch(void* const* d_in, const int* in_sizes, int n_in,
                              void* d_out, int out_size)
{
    const float* wave   = (const float*)d_in[0];
    const float* phases = (const float*)d_in[1];
    const float* mask   = (const float*)d_in[2];
    float* out = (float*)d_out;

    EncodeFn enc = nullptr;
    cudaDriverEntryPointQueryResult qr;
    cudaGetDriverEntryPoint("cuTensorMapEncodeTiled", (void**)&enc, cudaEnableDefault, &qr);

    CUtensorMap mapW, mapO;
    make_map(enc, &mapW, (void*)wave);
    make_map(enc, &mapO, (void*)out);

    cudaFuncSetAttribute(surrogate_kernel,
                         cudaFuncAttributeMaxDynamicSharedMemorySize, SMEM_TOTAL);
    surrogate_kernel<<<1024, BDIM, SMEM_TOTAL>>>(wave, phases, mask, out, mapW, mapO);
}